// round 15
// baseline (speedup 1.0000x reference)
#include <cuda_runtime.h>
#include <cuda_bf16.h>
#include <cuda_fp16.h>
#include <cstdint>

#define NN 100000
#define EE 3200000
#define DD 256
#define D4 64
#define SCB 391   // ceil(NN/256)
#define WSZ (DD * DD)

__device__ int    g_deg[NN];
__device__ int    g_off[NN + 1];
__device__ int    g_cur[NN];
__device__ int    g_srcs[EE];
__device__ int    g_part[SCB];
__device__ float4 g_agg4[(size_t)NN * D4];
__device__ float4 g_h4[(size_t)NN * D4];
__device__ uint2  g_x16[(size_t)NN * D4];   // fp16 x (row = 64 uint2)
__device__ uint2  g_h16[(size_t)NN * D4];   // fp16 h
// pre-split weights: [0]=Wl1 [1]=Wr1 [2]=Wl2 [3]=Wr2
__device__ __nv_bfloat16 g_wh[4][WSZ];
__device__ __nv_bfloat16 g_wl[4][WSZ];

// ---------------- CSC build ----------------
__global__ void k_zero() {
    int i = blockIdx.x * blockDim.x + threadIdx.x;
    if (i < NN) { g_deg[i] = 0; g_cur[i] = 0; }
}

// fused: convert x -> fp16 (6.4M threads) AND degree histogram (first 3.2M threads)
__global__ void __launch_bounds__(256) k_deg_cvt(const int* __restrict__ ei,
                                                 const float4* __restrict__ in,
                                                 uint2* __restrict__ out16) {
    int i = blockIdx.x * blockDim.x + threadIdx.x;
    if (i < NN * D4) {
        float4 a = in[i];
        __half2 h0 = __floats2half2_rn(a.x, a.y);
        __half2 h1 = __floats2half2_rn(a.z, a.w);
        uint2 o;
        o.x = *(unsigned*)&h0;
        o.y = *(unsigned*)&h1;
        out16[i] = o;
    }
    if (i < EE) {
        int t = ei[EE + i];
        if (t >= 0 && t < NN) atomicAdd(&g_deg[t], 1);
    }
}

// pre-split the 4 weight matrices into bf16 hi/lo (once per launch)
__global__ void __launch_bounds__(256) k_wsplit(const float* __restrict__ w0,
                                                const float* __restrict__ w1,
                                                const float* __restrict__ w2,
                                                const float* __restrict__ w3) {
    int i = blockIdx.x * blockDim.x + threadIdx.x;
    if (i >= 4 * WSZ) return;
    int m = i >> 16;          // WSZ = 65536
    int e = i & (WSZ - 1);
    const float* src = (m == 0) ? w0 : (m == 1) ? w1 : (m == 2) ? w2 : w3;
    float v = src[e];
    __nv_bfloat16 h = __float2bfloat16(v);
    float lv = v - __bfloat162float(h);
    g_wh[m][e] = h;
    g_wl[m][e] = __float2bfloat16(lv);
}

__global__ void __launch_bounds__(256) k_scan1() {
    __shared__ int sh[256];
    int i = blockIdx.x * 256 + threadIdx.x;
    sh[threadIdx.x] = (i < NN) ? g_deg[i] : 0;
    __syncthreads();
    for (int d = 128; d > 0; d >>= 1) {
        if (threadIdx.x < d) sh[threadIdx.x] += sh[threadIdx.x + d];
        __syncthreads();
    }
    if (threadIdx.x == 0) g_part[blockIdx.x] = sh[0];
}

__global__ void __launch_bounds__(512) k_scan2b() {
    __shared__ int sh[512];
    int tid = threadIdx.x;
    int own = (tid < SCB) ? g_part[tid] : 0;
    sh[tid] = own;
    __syncthreads();
    for (int d = 1; d < 512; d <<= 1) {
        int v = (tid >= d) ? sh[tid - d] : 0;
        __syncthreads();
        sh[tid] += v;
        __syncthreads();
    }
    if (tid < SCB) g_part[tid] = sh[tid] - own;
}

__global__ void __launch_bounds__(256) k_scan3() {
    __shared__ int sh[256];
    int i = blockIdx.x * 256 + threadIdx.x;
    int own = (i < NN) ? g_deg[i] : 0;
    sh[threadIdx.x] = own;
    __syncthreads();
    for (int d = 1; d < 256; d <<= 1) {
        int v = (threadIdx.x >= d) ? sh[threadIdx.x - d] : 0;
        __syncthreads();
        sh[threadIdx.x] += v;
        __syncthreads();
    }
    if (i < NN) g_off[i] = g_part[blockIdx.x] + sh[threadIdx.x] - own;
    if (i == NN - 1) g_off[NN] = EE;
}

__global__ void k_scatter(const int* __restrict__ ei) {
    int e = blockIdx.x * blockDim.x + threadIdx.x;
    if (e < EE) {
        int t = ei[EE + e];
        int s = ei[e];
        if (t >= 0 && t < NN && s >= 0 && s < NN) {
            int p = atomicAdd(&g_cur[t], 1);
            g_srcs[g_off[t] + p] = s;
        }
    }
}

// ---------------- mean aggregation: fp16 gather, fp32 accum/out, 8-edge unroll ----------------
__global__ void __launch_bounds__(256) k_agg16(const uint2* __restrict__ x16,
                                               float4* __restrict__ out4) {
    int node = blockIdx.x * 4 + (threadIdx.x >> 6);
    int t = threadIdx.x & 63;
    if (node >= NN) return;
    int beg = g_off[node];
    int end = g_off[node + 1];

    float4 a = make_float4(0.f, 0.f, 0.f, 0.f);
    float4 b = make_float4(0.f, 0.f, 0.f, 0.f);
    int i = beg;
    for (; i + 8 <= end; i += 8) {
        uint2 v0 = x16[(size_t)g_srcs[i]     * D4 + t];
        uint2 v1 = x16[(size_t)g_srcs[i + 1] * D4 + t];
        uint2 v2 = x16[(size_t)g_srcs[i + 2] * D4 + t];
        uint2 v3 = x16[(size_t)g_srcs[i + 3] * D4 + t];
        uint2 v4 = x16[(size_t)g_srcs[i + 4] * D4 + t];
        uint2 v5 = x16[(size_t)g_srcs[i + 5] * D4 + t];
        uint2 v6 = x16[(size_t)g_srcs[i + 6] * D4 + t];
        uint2 v7 = x16[(size_t)g_srcs[i + 7] * D4 + t];
        float2 f;
        f = __half22float2(*(__half2*)&v0.x); a.x += f.x; a.y += f.y;
        f = __half22float2(*(__half2*)&v0.y); a.z += f.x; a.w += f.y;
        f = __half22float2(*(__half2*)&v1.x); b.x += f.x; b.y += f.y;
        f = __half22float2(*(__half2*)&v1.y); b.z += f.x; b.w += f.y;
        f = __half22float2(*(__half2*)&v2.x); a.x += f.x; a.y += f.y;
        f = __half22float2(*(__half2*)&v2.y); a.z += f.x; a.w += f.y;
        f = __half22float2(*(__half2*)&v3.x); b.x += f.x; b.y += f.y;
        f = __half22float2(*(__half2*)&v3.y); b.z += f.x; b.w += f.y;
        f = __half22float2(*(__half2*)&v4.x); a.x += f.x; a.y += f.y;
        f = __half22float2(*(__half2*)&v4.y); a.z += f.x; a.w += f.y;
        f = __half22float2(*(__half2*)&v5.x); b.x += f.x; b.y += f.y;
        f = __half22float2(*(__half2*)&v5.y); b.z += f.x; b.w += f.y;
        f = __half22float2(*(__half2*)&v6.x); a.x += f.x; a.y += f.y;
        f = __half22float2(*(__half2*)&v6.y); a.z += f.x; a.w += f.y;
        f = __half22float2(*(__half2*)&v7.x); b.x += f.x; b.y += f.y;
        f = __half22float2(*(__half2*)&v7.y); b.z += f.x; b.w += f.y;
    }
    for (; i < end; i++) {
        uint2 v = x16[(size_t)g_srcs[i] * D4 + t];
        float2 f;
        f = __half22float2(*(__half2*)&v.x); a.x += f.x; a.y += f.y;
        f = __half22float2(*(__half2*)&v.y); a.z += f.x; a.w += f.y;
    }
    float inv = 1.0f / fmaxf((float)(end - beg), 1.0f);
    float4 r;
    r.x = (a.x + b.x) * inv;
    r.y = (a.y + b.y) * inv;
    r.z = (a.z + b.z) * inv;
    r.w = (a.w + b.w) * inv;
    out4[(size_t)node * D4 + t] = r;
}

// ---------------- tensor-core fused dual GEMM ----------------
// fp32 A/X (split in loader), PRE-SPLIT bf16 weights (pure-copy B loader).
// Grid (2, 782): x = column block, y = row block (L2 reuse of A/X).
#define BM 128
#define BN 128
#define BK 32
#define APAD 40
#define BPAD 136

__device__ __forceinline__ unsigned sptr(const void* p) {
    return (unsigned)__cvta_generic_to_shared(p);
}

__device__ __forceinline__ void ldm_x4(unsigned* r, unsigned addr) {
    asm volatile("ldmatrix.sync.aligned.m8n8.x4.shared.b16 {%0,%1,%2,%3}, [%4];"
                 : "=r"(r[0]), "=r"(r[1]), "=r"(r[2]), "=r"(r[3])
                 : "r"(addr));
}

__device__ __forceinline__ void ldm_x4t(unsigned* r, unsigned addr) {
    asm volatile("ldmatrix.sync.aligned.m8n8.x4.trans.shared.b16 {%0,%1,%2,%3}, [%4];"
                 : "=r"(r[0]), "=r"(r[1]), "=r"(r[2]), "=r"(r[3])
                 : "r"(addr));
}

__device__ __forceinline__ void mma_bf16(float* d, const unsigned* a, const unsigned* b) {
    asm volatile("mma.sync.aligned.m16n8k16.row.col.f32.bf16.bf16.f32 "
                 "{%0,%1,%2,%3}, {%4,%5,%6,%7}, {%8,%9}, {%0,%1,%2,%3};"
                 : "+f"(d[0]), "+f"(d[1]), "+f"(d[2]), "+f"(d[3])
                 : "r"(a[0]), "r"(a[1]), "r"(a[2]), "r"(a[3]),
                   "r"(b[0]), "r"(b[1]));
}

__device__ __forceinline__ void split2(float x, float y, unsigned* hi, unsigned* lo) {
    __nv_bfloat16 hx = __float2bfloat16(x);
    __nv_bfloat16 hy = __float2bfloat16(y);
    float lx = x - __bfloat162float(hx);
    float ly = y - __bfloat162float(hy);
    __nv_bfloat162 h2 = __halves2bfloat162(hx, hy);
    __nv_bfloat162 l2 = __halves2bfloat162(__float2bfloat16(lx), __float2bfloat16(ly));
    *hi = *(unsigned*)&h2;
    *lo = *(unsigned*)&l2;
}

__global__ void __launch_bounds__(256) k_gemm_tc(const float* __restrict__ A,
                                                 const float* __restrict__ X,
                                                 const __nv_bfloat16* __restrict__ W1h,
                                                 const __nv_bfloat16* __restrict__ W1l,
                                                 const __nv_bfloat16* __restrict__ W2h,
                                                 const __nv_bfloat16* __restrict__ W2l,
                                                 const float* __restrict__ bias,
                                                 float* __restrict__ O,
                                                 __half* __restrict__ O16,
                                                 int do_relu) {
    __shared__ __nv_bfloat16 Ah[BM][APAD];
    __shared__ __nv_bfloat16 Al[BM][APAD];
    __shared__ __nv_bfloat16 Bh[BK][BPAD];
    __shared__ __nv_bfloat16 Bl[BK][BPAD];

    int tid = threadIdx.x;
    int wid = tid >> 5;
    int lane = tid & 31;
    int warp_m = wid >> 1;
    int warp_n = wid & 1;
    int row0 = blockIdx.y * BM;
    int col0 = blockIdx.x * BN;

    float acc[2][8][4];
    for (int i = 0; i < 2; i++) {
        for (int j = 0; j < 8; j++) {
            for (int q = 0; q < 4; q++) {
                acc[i][j][q] = 0.f;
            }
        }
    }

    int ar = tid >> 1;
    int ac = (tid & 1) * 16;
    int br = tid >> 3;
    int bc = (tid & 7) * 16;

    for (int phase = 0; phase < 2; phase++) {
        const float* Ain = phase ? X : A;
        const __nv_bfloat16* Winh = phase ? W2h : W1h;
        const __nv_bfloat16* Winl = phase ? W2l : W1l;

        for (int kt = 0; kt < DD; kt += BK) {
            // A tile (fp32 -> bf16 hi/lo split)
            int gr = row0 + ar;
            const float* asrc = Ain + (size_t)gr * DD + kt + ac;
            for (int q = 0; q < 4; q++) {
                float4 v = make_float4(0.f, 0.f, 0.f, 0.f);
                if (gr < NN) v = *(const float4*)(asrc + q * 4);
                unsigned h01, l01, h23, l23;
                split2(v.x, v.y, &h01, &l01);
                split2(v.z, v.w, &h23, &l23);
                int c = ac + q * 4;
                *(unsigned*)&Ah[ar][c]     = h01;
                *(unsigned*)&Ah[ar][c + 2] = h23;
                *(unsigned*)&Al[ar][c]     = l01;
                *(unsigned*)&Al[ar][c + 2] = l23;
            }
            // B tile: pure copy of pre-split weights (2x uint4 per stream = 16 bf16)
            {
                size_t off = (size_t)(kt + br) * DD + col0 + bc;
                const uint4* hsrc = (const uint4*)(Winh + off);
                const uint4* lsrc = (const uint4*)(Winl + off);
                uint4 h0 = hsrc[0];
                uint4 h1 = hsrc[1];
                uint4 l0 = lsrc[0];
                uint4 l1 = lsrc[1];
                *(uint4*)&Bh[br][bc]     = h0;
                *(uint4*)&Bh[br][bc + 8] = h1;
                *(uint4*)&Bl[br][bc]     = l0;
                *(uint4*)&Bl[br][bc + 8] = l1;
            }
            __syncthreads();

            for (int ks = 0; ks < BK; ks += 16) {
                unsigned ah[2][4];
                unsigned al[2][4];
                for (int i = 0; i < 2; i++) {
                    int r = warp_m * 32 + i * 16 + (lane & 15);
                    int c = ks + ((lane >> 4) << 3);
                    ldm_x4(ah[i], sptr(&Ah[r][c]));
                    ldm_x4(al[i], sptr(&Al[r][c]));
                }
                unsigned bh[8][2];
                unsigned bl[8][2];
                for (int j2 = 0; j2 < 4; j2++) {
                    int r = ks + (lane & 15);
                    int c = warp_n * 64 + j2 * 16 + ((lane >> 4) << 3);
                    unsigned t4[4];
                    ldm_x4t(t4, sptr(&Bh[r][c]));
                    bh[j2 * 2][0]     = t4[0];
                    bh[j2 * 2][1]     = t4[1];
                    bh[j2 * 2 + 1][0] = t4[2];
                    bh[j2 * 2 + 1][1] = t4[3];
                    ldm_x4t(t4, sptr(&Bl[r][c]));
                    bl[j2 * 2][0]     = t4[0];
                    bl[j2 * 2][1]     = t4[1];
                    bl[j2 * 2 + 1][0] = t4[2];
                    bl[j2 * 2 + 1][1] = t4[3];
                }
                for (int i = 0; i < 2; i++) {
                    for (int j = 0; j < 8; j++) {
                        mma_bf16(acc[i][j], ah[i], bh[j]);
                        mma_bf16(acc[i][j], ah[i], bl[j]);
                        mma_bf16(acc[i][j], al[i], bh[j]);
                    }
                }
            }
            __syncthreads();
        }
    }

    for (int j = 0; j < 8; j++) {
        int c = col0 + warp_n * 64 + j * 8 + (lane & 3) * 2;
        float2 bb = *(const float2*)(bias + c);
        for (int i = 0; i < 2; i++) {
            int r = row0 + warp_m * 32 + i * 16 + (lane >> 2);
            float v0 = acc[i][j][0] + bb.x;
            float v1 = acc[i][j][1] + bb.y;
            float v2 = acc[i][j][2] + bb.x;
            float v3 = acc[i][j][3] + bb.y;
            if (do_relu) {
                v0 = fmaxf(v0, 0.f);
                v1 = fmaxf(v1, 0.f);
                v2 = fmaxf(v2, 0.f);
                v3 = fmaxf(v3, 0.f);
            }
            if (r < NN) {
                *(float2*)(O + (size_t)r * DD + c) = make_float2(v0, v1);
                if (O16) {
                    __half2 hh = __floats2half2_rn(v0, v1);
                    *(__half2*)(O16 + (size_t)r * DD + c) = hh;
                }
            }
            if (r + 8 < NN) {
                *(float2*)(O + (size_t)(r + 8) * DD + c) = make_float2(v2, v3);
                if (O16) {
                    __half2 hh = __floats2half2_rn(v2, v3);
                    *(__half2*)(O16 + (size_t)(r + 8) * DD + c) = hh;
                }
            }
        }
    }
}

extern "C" void kernel_launch(void* const* d_in, const int* in_sizes, int n_in,
                              void* d_out, int out_size) {
    const float* x   = (const float*)d_in[0];
    const int*   ei  = (const int*)d_in[1];
    const float* Wl1 = (const float*)d_in[2];
    const float* b1  = (const float*)d_in[3];
    const float* Wr1 = (const float*)d_in[4];
    const float* Wl2 = (const float*)d_in[5];
    const float* b2  = (const float*)d_in[6];
    const float* Wr2 = (const float*)d_in[7];
    float*       out = (float*)d_out;

    void* agg_p = 0;
    void* h_p = 0;
    void* x16_p = 0;
    void* h16_p = 0;
    void* wh_p = 0;
    void* wl_p = 0;
    cudaGetSymbolAddress(&agg_p, g_agg4);
    cudaGetSymbolAddress(&h_p, g_h4);
    cudaGetSymbolAddress(&x16_p, g_x16);
    cudaGetSymbolAddress(&h16_p, g_h16);
    cudaGetSymbolAddress(&wh_p, g_wh);
    cudaGetSymbolAddress(&wl_p, g_wl);
    float4* agg4 = (float4*)agg_p;
    float4* h4   = (float4*)h_p;
    uint2*  x16  = (uint2*)x16_p;
    uint2*  h16  = (uint2*)h16_p;
    __nv_bfloat16* wh = (__nv_bfloat16*)wh_p;
    __nv_bfloat16* wl = (__nv_bfloat16*)wl_p;

    k_zero<<<(NN + 255) / 256, 256>>>();
    k_deg_cvt<<<(NN * D4 + 255) / 256, 256>>>(ei, (const float4*)x, x16);
    k_wsplit<<<(4 * WSZ + 255) / 256, 256>>>(Wl1, Wr1, Wl2, Wr2);
    k_scan1<<<SCB, 256>>>();
    k_scan2b<<<1, 512>>>();
    k_scan3<<<SCB, 256>>>();
    k_scatter<<<(EE + 255) / 256, 256>>>(ei);

    dim3 ggrid(DD / BN, (NN + BM - 1) / BM);   // (2, 782)

    // layer 1: agg(x16) -> agg4; gemm(A=agg4 w/ Wl1, X=x w/ Wr1) -> h4 + h16 (+relu)
    k_agg16<<<(NN + 3) / 4, 256>>>(x16, agg4);
    k_gemm_tc<<<ggrid, 256>>>((const float*)agg4, x,
                              wh + 0 * WSZ, wl + 0 * WSZ,
                              wh + 1 * WSZ, wl + 1 * WSZ,
                              b1, (float*)h4, (__half*)h16, 1);

    // layer 2: agg(h16) -> agg4; gemm(A=agg4 w/ Wl2, X=h4 w/ Wr2) -> out
    k_agg16<<<(NN + 3) / 4, 256>>>(h16, agg4);
    k_gemm_tc<<<ggrid, 256>>>((const float*)agg4, (const float*)h4,
                              wh + 2 * WSZ, wl + 2 * WSZ,
                              wh + 3 * WSZ, wl + 3 * WSZ,
                              b2, out, (__half*)0, 0);
}

// round 16
// speedup vs baseline: 1.1926x; 1.1926x over previous
#include <cuda_runtime.h>
#include <cuda_bf16.h>
#include <cuda_fp16.h>
#include <cstdint>

#define NN 100000
#define EE 3200000
#define DD 256
#define D4 64
#define SCB 391   // ceil(NN/256)
#define WSZ (DD * DD)

__device__ int    g_deg[NN];
__device__ int    g_off[NN + 1];
__device__ int    g_cur[NN];
__device__ int    g_srcs[EE];
__device__ int    g_part[SCB];
__device__ float4 g_agg4[(size_t)NN * D4];
__device__ float4 g_h4[(size_t)NN * D4];
__device__ uint2  g_x16[(size_t)NN * D4];   // fp16 x (row = 64 uint2)
__device__ uint2  g_h16[(size_t)NN * D4];   // fp16 h
// pre-split weights: [0]=Wl1 [1]=Wr1 [2]=Wl2 [3]=Wr2
__device__ __nv_bfloat16 g_wh[4][WSZ];
__device__ __nv_bfloat16 g_wl[4][WSZ];

// ---------------- CSC build ----------------
__global__ void k_zero() {
    int i = blockIdx.x * blockDim.x + threadIdx.x;
    if (i < NN) { g_deg[i] = 0; g_cur[i] = 0; }
}

// fused: convert x -> fp16 (6.4M threads) AND degree histogram (first 3.2M threads)
__global__ void __launch_bounds__(256) k_deg_cvt(const int* __restrict__ ei,
                                                 const float4* __restrict__ in,
                                                 uint2* __restrict__ out16) {
    int i = blockIdx.x * blockDim.x + threadIdx.x;
    if (i < NN * D4) {
        float4 a = in[i];
        __half2 h0 = __floats2half2_rn(a.x, a.y);
        __half2 h1 = __floats2half2_rn(a.z, a.w);
        uint2 o;
        o.x = *(unsigned*)&h0;
        o.y = *(unsigned*)&h1;
        out16[i] = o;
    }
    if (i < EE) {
        int t = ei[EE + i];
        if (t >= 0 && t < NN) atomicAdd(&g_deg[t], 1);
    }
}

// pre-split the 4 weight matrices into bf16 hi/lo (once per launch)
__global__ void __launch_bounds__(256) k_wsplit(const float* __restrict__ w0,
                                                const float* __restrict__ w1,
                                                const float* __restrict__ w2,
                                                const float* __restrict__ w3) {
    int i = blockIdx.x * blockDim.x + threadIdx.x;
    if (i >= 4 * WSZ) return;
    int m = i >> 16;          // WSZ = 65536
    int e = i & (WSZ - 1);
    const float* src = (m == 0) ? w0 : (m == 1) ? w1 : (m == 2) ? w2 : w3;
    float v = src[e];
    __nv_bfloat16 h = __float2bfloat16(v);
    float lv = v - __bfloat162float(h);
    g_wh[m][e] = h;
    g_wl[m][e] = __float2bfloat16(lv);
}

__global__ void __launch_bounds__(256) k_scan1() {
    __shared__ int sh[256];
    int i = blockIdx.x * 256 + threadIdx.x;
    sh[threadIdx.x] = (i < NN) ? g_deg[i] : 0;
    __syncthreads();
    for (int d = 128; d > 0; d >>= 1) {
        if (threadIdx.x < d) sh[threadIdx.x] += sh[threadIdx.x + d];
        __syncthreads();
    }
    if (threadIdx.x == 0) g_part[blockIdx.x] = sh[0];
}

__global__ void __launch_bounds__(512) k_scan2b() {
    __shared__ int sh[512];
    int tid = threadIdx.x;
    int own = (tid < SCB) ? g_part[tid] : 0;
    sh[tid] = own;
    __syncthreads();
    for (int d = 1; d < 512; d <<= 1) {
        int v = (tid >= d) ? sh[tid - d] : 0;
        __syncthreads();
        sh[tid] += v;
        __syncthreads();
    }
    if (tid < SCB) g_part[tid] = sh[tid] - own;
}

__global__ void __launch_bounds__(256) k_scan3() {
    __shared__ int sh[256];
    int i = blockIdx.x * 256 + threadIdx.x;
    int own = (i < NN) ? g_deg[i] : 0;
    sh[threadIdx.x] = own;
    __syncthreads();
    for (int d = 1; d < 256; d <<= 1) {
        int v = (threadIdx.x >= d) ? sh[threadIdx.x - d] : 0;
        __syncthreads();
        sh[threadIdx.x] += v;
        __syncthreads();
    }
    if (i < NN) g_off[i] = g_part[blockIdx.x] + sh[threadIdx.x] - own;
    if (i == NN - 1) g_off[NN] = EE;
}

__global__ void k_scatter(const int* __restrict__ ei) {
    int e = blockIdx.x * blockDim.x + threadIdx.x;
    if (e < EE) {
        int t = ei[EE + e];
        int s = ei[e];
        if (t >= 0 && t < NN && s >= 0 && s < NN) {
            int p = atomicAdd(&g_cur[t], 1);
            g_srcs[g_off[t] + p] = s;
        }
    }
}

// ---------------- mean aggregation: fp16 gather, fp32 accum/out, 8-edge unroll ----------------
__global__ void __launch_bounds__(256) k_agg16(const uint2* __restrict__ x16,
                                               float4* __restrict__ out4) {
    int node = blockIdx.x * 4 + (threadIdx.x >> 6);
    int t = threadIdx.x & 63;
    if (node >= NN) return;
    int beg = g_off[node];
    int end = g_off[node + 1];

    float4 a = make_float4(0.f, 0.f, 0.f, 0.f);
    float4 b = make_float4(0.f, 0.f, 0.f, 0.f);
    int i = beg;
    for (; i + 8 <= end; i += 8) {
        uint2 v0 = x16[(size_t)g_srcs[i]     * D4 + t];
        uint2 v1 = x16[(size_t)g_srcs[i + 1] * D4 + t];
        uint2 v2 = x16[(size_t)g_srcs[i + 2] * D4 + t];
        uint2 v3 = x16[(size_t)g_srcs[i + 3] * D4 + t];
        uint2 v4 = x16[(size_t)g_srcs[i + 4] * D4 + t];
        uint2 v5 = x16[(size_t)g_srcs[i + 5] * D4 + t];
        uint2 v6 = x16[(size_t)g_srcs[i + 6] * D4 + t];
        uint2 v7 = x16[(size_t)g_srcs[i + 7] * D4 + t];
        float2 f;
        f = __half22float2(*(__half2*)&v0.x); a.x += f.x; a.y += f.y;
        f = __half22float2(*(__half2*)&v0.y); a.z += f.x; a.w += f.y;
        f = __half22float2(*(__half2*)&v1.x); b.x += f.x; b.y += f.y;
        f = __half22float2(*(__half2*)&v1.y); b.z += f.x; b.w += f.y;
        f = __half22float2(*(__half2*)&v2.x); a.x += f.x; a.y += f.y;
        f = __half22float2(*(__half2*)&v2.y); a.z += f.x; a.w += f.y;
        f = __half22float2(*(__half2*)&v3.x); b.x += f.x; b.y += f.y;
        f = __half22float2(*(__half2*)&v3.y); b.z += f.x; b.w += f.y;
        f = __half22float2(*(__half2*)&v4.x); a.x += f.x; a.y += f.y;
        f = __half22float2(*(__half2*)&v4.y); a.z += f.x; a.w += f.y;
        f = __half22float2(*(__half2*)&v5.x); b.x += f.x; b.y += f.y;
        f = __half22float2(*(__half2*)&v5.y); b.z += f.x; b.w += f.y;
        f = __half22float2(*(__half2*)&v6.x); a.x += f.x; a.y += f.y;
        f = __half22float2(*(__half2*)&v6.y); a.z += f.x; a.w += f.y;
        f = __half22float2(*(__half2*)&v7.x); b.x += f.x; b.y += f.y;
        f = __half22float2(*(__half2*)&v7.y); b.z += f.x; b.w += f.y;
    }
    for (; i < end; i++) {
        uint2 v = x16[(size_t)g_srcs[i] * D4 + t];
        float2 f;
        f = __half22float2(*(__half2*)&v.x); a.x += f.x; a.y += f.y;
        f = __half22float2(*(__half2*)&v.y); a.z += f.x; a.w += f.y;
    }
    float inv = 1.0f / fmaxf((float)(end - beg), 1.0f);
    float4 r;
    r.x = (a.x + b.x) * inv;
    r.y = (a.y + b.y) * inv;
    r.z = (a.z + b.z) * inv;
    r.w = (a.w + b.w) * inv;
    out4[(size_t)node * D4 + t] = r;
}

// ---------------- tensor-core fused dual GEMM ----------------
// fp32 A/X (split in loader), pre-split bf16 weights with REGISTER-SAFE copy
// loader (4 iterations, one uint2 hi + one uint2 lo per iteration).
// Grid (2, 782): x = column block, y = row block (L2 reuse of A/X).
#define BM 128
#define BN 128
#define BK 32
#define APAD 40
#define BPAD 136

__device__ __forceinline__ unsigned sptr(const void* p) {
    return (unsigned)__cvta_generic_to_shared(p);
}

__device__ __forceinline__ void ldm_x4(unsigned* r, unsigned addr) {
    asm volatile("ldmatrix.sync.aligned.m8n8.x4.shared.b16 {%0,%1,%2,%3}, [%4];"
                 : "=r"(r[0]), "=r"(r[1]), "=r"(r[2]), "=r"(r[3])
                 : "r"(addr));
}

__device__ __forceinline__ void ldm_x4t(unsigned* r, unsigned addr) {
    asm volatile("ldmatrix.sync.aligned.m8n8.x4.trans.shared.b16 {%0,%1,%2,%3}, [%4];"
                 : "=r"(r[0]), "=r"(r[1]), "=r"(r[2]), "=r"(r[3])
                 : "r"(addr));
}

__device__ __forceinline__ void mma_bf16(float* d, const unsigned* a, const unsigned* b) {
    asm volatile("mma.sync.aligned.m16n8k16.row.col.f32.bf16.bf16.f32 "
                 "{%0,%1,%2,%3}, {%4,%5,%6,%7}, {%8,%9}, {%0,%1,%2,%3};"
                 : "+f"(d[0]), "+f"(d[1]), "+f"(d[2]), "+f"(d[3])
                 : "r"(a[0]), "r"(a[1]), "r"(a[2]), "r"(a[3]),
                   "r"(b[0]), "r"(b[1]));
}

__device__ __forceinline__ void split2(float x, float y, unsigned* hi, unsigned* lo) {
    __nv_bfloat16 hx = __float2bfloat16(x);
    __nv_bfloat16 hy = __float2bfloat16(y);
    float lx = x - __bfloat162float(hx);
    float ly = y - __bfloat162float(hy);
    __nv_bfloat162 h2 = __halves2bfloat162(hx, hy);
    __nv_bfloat162 l2 = __halves2bfloat162(__float2bfloat16(lx), __float2bfloat16(ly));
    *hi = *(unsigned*)&h2;
    *lo = *(unsigned*)&l2;
}

__global__ void __launch_bounds__(256) k_gemm_tc(const float* __restrict__ A,
                                                 const float* __restrict__ X,
                                                 const __nv_bfloat16* __restrict__ W1h,
                                                 const __nv_bfloat16* __restrict__ W1l,
                                                 const __nv_bfloat16* __restrict__ W2h,
                                                 const __nv_bfloat16* __restrict__ W2l,
                                                 const float* __restrict__ bias,
                                                 float* __restrict__ O,
                                                 __half* __restrict__ O16,
                                                 int do_relu) {
    __shared__ __nv_bfloat16 Ah[BM][APAD];
    __shared__ __nv_bfloat16 Al[BM][APAD];
    __shared__ __nv_bfloat16 Bh[BK][BPAD];
    __shared__ __nv_bfloat16 Bl[BK][BPAD];

    int tid = threadIdx.x;
    int wid = tid >> 5;
    int lane = tid & 31;
    int warp_m = wid >> 1;
    int warp_n = wid & 1;
    int row0 = blockIdx.y * BM;
    int col0 = blockIdx.x * BN;

    float acc[2][8][4];
    for (int i = 0; i < 2; i++) {
        for (int j = 0; j < 8; j++) {
            for (int q = 0; q < 4; q++) {
                acc[i][j][q] = 0.f;
            }
        }
    }

    int ar = tid >> 1;
    int ac = (tid & 1) * 16;
    int br = tid >> 3;
    int bc = (tid & 7) * 16;

    for (int phase = 0; phase < 2; phase++) {
        const float* Ain = phase ? X : A;
        const __nv_bfloat16* Winh = phase ? W2h : W1h;
        const __nv_bfloat16* Winl = phase ? W2l : W1l;

        for (int kt = 0; kt < DD; kt += BK) {
            // A tile (fp32 -> bf16 hi/lo split) — R14-proven shape
            int gr = row0 + ar;
            const float* asrc = Ain + (size_t)gr * DD + kt + ac;
            for (int q = 0; q < 4; q++) {
                float4 v = make_float4(0.f, 0.f, 0.f, 0.f);
                if (gr < NN) v = *(const float4*)(asrc + q * 4);
                unsigned h01, l01, h23, l23;
                split2(v.x, v.y, &h01, &l01);
                split2(v.z, v.w, &h23, &l23);
                int c = ac + q * 4;
                *(unsigned*)&Ah[ar][c]     = h01;
                *(unsigned*)&Ah[ar][c + 2] = h23;
                *(unsigned*)&Al[ar][c]     = l01;
                *(unsigned*)&Al[ar][c + 2] = l23;
            }
            // B tile: copy pre-split weights, 4 iterations x (uint2 hi + uint2 lo)
            {
                size_t off = (size_t)(kt + br) * DD + col0 + bc;
                const __nv_bfloat16* hsrc = Winh + off;
                const __nv_bfloat16* lsrc = Winl + off;
                for (int q = 0; q < 4; q++) {
                    uint2 hv = *(const uint2*)(hsrc + q * 4);
                    uint2 lv = *(const uint2*)(lsrc + q * 4);
                    int c = bc + q * 4;
                    *(uint2*)&Bh[br][c] = hv;
                    *(uint2*)&Bl[br][c] = lv;
                }
            }
            __syncthreads();

            for (int ks = 0; ks < BK; ks += 16) {
                unsigned ah[2][4];
                unsigned al[2][4];
                for (int i = 0; i < 2; i++) {
                    int r = warp_m * 32 + i * 16 + (lane & 15);
                    int c = ks + ((lane >> 4) << 3);
                    ldm_x4(ah[i], sptr(&Ah[r][c]));
                    ldm_x4(al[i], sptr(&Al[r][c]));
                }
                unsigned bh[8][2];
                unsigned bl[8][2];
                for (int j2 = 0; j2 < 4; j2++) {
                    int r = ks + (lane & 15);
                    int c = warp_n * 64 + j2 * 16 + ((lane >> 4) << 3);
                    unsigned t4[4];
                    ldm_x4t(t4, sptr(&Bh[r][c]));
                    bh[j2 * 2][0]     = t4[0];
                    bh[j2 * 2][1]     = t4[1];
                    bh[j2 * 2 + 1][0] = t4[2];
                    bh[j2 * 2 + 1][1] = t4[3];
                    ldm_x4t(t4, sptr(&Bl[r][c]));
                    bl[j2 * 2][0]     = t4[0];
                    bl[j2 * 2][1]     = t4[1];
                    bl[j2 * 2 + 1][0] = t4[2];
                    bl[j2 * 2 + 1][1] = t4[3];
                }
                for (int i = 0; i < 2; i++) {
                    for (int j = 0; j < 8; j++) {
                        mma_bf16(acc[i][j], ah[i], bh[j]);
                        mma_bf16(acc[i][j], ah[i], bl[j]);
                        mma_bf16(acc[i][j], al[i], bh[j]);
                    }
                }
            }
            __syncthreads();
        }
    }

    for (int j = 0; j < 8; j++) {
        int c = col0 + warp_n * 64 + j * 8 + (lane & 3) * 2;
        float2 bb = *(const float2*)(bias + c);
        for (int i = 0; i < 2; i++) {
            int r = row0 + warp_m * 32 + i * 16 + (lane >> 2);
            float v0 = acc[i][j][0] + bb.x;
            float v1 = acc[i][j][1] + bb.y;
            float v2 = acc[i][j][2] + bb.x;
            float v3 = acc[i][j][3] + bb.y;
            if (do_relu) {
                v0 = fmaxf(v0, 0.f);
                v1 = fmaxf(v1, 0.f);
                v2 = fmaxf(v2, 0.f);
                v3 = fmaxf(v3, 0.f);
            }
            if (r < NN) {
                *(float2*)(O + (size_t)r * DD + c) = make_float2(v0, v1);
                if (O16) {
                    __half2 hh = __floats2half2_rn(v0, v1);
                    *(__half2*)(O16 + (size_t)r * DD + c) = hh;
                }
            }
            if (r + 8 < NN) {
                *(float2*)(O + (size_t)(r + 8) * DD + c) = make_float2(v2, v3);
                if (O16) {
                    __half2 hh = __floats2half2_rn(v2, v3);
                    *(__half2*)(O16 + (size_t)(r + 8) * DD + c) = hh;
                }
            }
        }
    }
}

extern "C" void kernel_launch(void* const* d_in, const int* in_sizes, int n_in,
                              void* d_out, int out_size) {
    const float* x   = (const float*)d_in[0];
    const int*   ei  = (const int*)d_in[1];
    const float* Wl1 = (const float*)d_in[2];
    const float* b1  = (const float*)d_in[3];
    const float* Wr1 = (const float*)d_in[4];
    const float* Wl2 = (const float*)d_in[5];
    const float* b2  = (const float*)d_in[6];
    const float* Wr2 = (const float*)d_in[7];
    float*       out = (float*)d_out;

    void* agg_p = 0;
    void* h_p = 0;
    void* x16_p = 0;
    void* h16_p = 0;
    void* wh_p = 0;
    void* wl_p = 0;
    cudaGetSymbolAddress(&agg_p, g_agg4);
    cudaGetSymbolAddress(&h_p, g_h4);
    cudaGetSymbolAddress(&x16_p, g_x16);
    cudaGetSymbolAddress(&h16_p, g_h16);
    cudaGetSymbolAddress(&wh_p, g_wh);
    cudaGetSymbolAddress(&wl_p, g_wl);
    float4* agg4 = (float4*)agg_p;
    float4* h4   = (float4*)h_p;
    uint2*  x16  = (uint2*)x16_p;
    uint2*  h16  = (uint2*)h16_p;
    __nv_bfloat16* wh = (__nv_bfloat16*)wh_p;
    __nv_bfloat16* wl = (__nv_bfloat16*)wl_p;

    k_zero<<<(NN + 255) / 256, 256>>>();
    k_deg_cvt<<<(NN * D4 + 255) / 256, 256>>>(ei, (const float4*)x, x16);
    k_wsplit<<<(4 * WSZ + 255) / 256, 256>>>(Wl1, Wr1, Wl2, Wr2);
    k_scan1<<<SCB, 256>>>();
    k_scan2b<<<1, 512>>>();
    k_scan3<<<SCB, 256>>>();
    k_scatter<<<(EE + 255) / 256, 256>>>(ei);

    dim3 ggrid(DD / BN, (NN + BM - 1) / BM);   // (2, 782)

    // layer 1: agg(x16) -> agg4; gemm(A=agg4 w/ Wl1, X=x w/ Wr1) -> h4 + h16 (+relu)
    k_agg16<<<(NN + 3) / 4, 256>>>(x16, agg4);
    k_gemm_tc<<<ggrid, 256>>>((const float*)agg4, x,
                              wh + 0 * WSZ, wl + 0 * WSZ,
                              wh + 1 * WSZ, wl + 1 * WSZ,
                              b1, (float*)h4, (__half*)h16, 1);

    // layer 2: agg(h16) -> agg4; gemm(A=agg4 w/ Wl2, X=h4 w/ Wr2) -> out
    k_agg16<<<(NN + 3) / 4, 256>>>(h16, agg4);
    k_gemm_tc<<<ggrid, 256>>>((const float*)agg4, (const float*)h4,
                              wh + 2 * WSZ, wl + 2 * WSZ,
                              wh + 3 * WSZ, wl + 3 * WSZ,
                              b2, out, (__half*)0, 0);
}

// round 17
// speedup vs baseline: 1.1979x; 1.0044x over previous
#include <cuda_runtime.h>
#include <cuda_bf16.h>
#include <cuda_fp16.h>
#include <cstdint>

#define NN 100000
#define EE 3200000
#define DD 256
#define D4 64
#define SCB 391   // ceil(NN/256)
#define WSZ (DD * DD)

__device__ int    g_deg[NN];
__device__ int    g_off[NN + 1];
__device__ int    g_cur[NN];
__device__ int    g_srcs[EE];
__device__ int    g_part[SCB];
__device__ float4 g_agg4[(size_t)NN * D4];
__device__ float4 g_h4[(size_t)NN * D4];
__device__ uint2  g_x16[(size_t)NN * D4];   // fp16 x (row = 64 uint2)
__device__ uint2  g_h16[(size_t)NN * D4];   // fp16 h
// pre-split weights: [0]=Wl1 [1]=Wr1 [2]=Wl2 [3]=Wr2
__device__ __nv_bfloat16 g_wh[4][WSZ];
__device__ __nv_bfloat16 g_wl[4][WSZ];

// ---------------- CSC build ----------------
__global__ void k_zero() {
    int i = blockIdx.x * blockDim.x + threadIdx.x;
    if (i < NN) { g_deg[i] = 0; g_cur[i] = 0; }
}

__global__ void __launch_bounds__(256) k_deg_cvt(const int* __restrict__ ei,
                                                 const float4* __restrict__ in,
                                                 uint2* __restrict__ out16) {
    int i = blockIdx.x * blockDim.x + threadIdx.x;
    if (i < NN * D4) {
        float4 a = in[i];
        __half2 h0 = __floats2half2_rn(a.x, a.y);
        __half2 h1 = __floats2half2_rn(a.z, a.w);
        uint2 o;
        o.x = *(unsigned*)&h0;
        o.y = *(unsigned*)&h1;
        out16[i] = o;
    }
    if (i < EE) {
        int t = ei[EE + i];
        if (t >= 0 && t < NN) atomicAdd(&g_deg[t], 1);
    }
}

__global__ void __launch_bounds__(256) k_wsplit(const float* __restrict__ w0,
                                                const float* __restrict__ w1,
                                                const float* __restrict__ w2,
                                                const float* __restrict__ w3) {
    int i = blockIdx.x * blockDim.x + threadIdx.x;
    if (i >= 4 * WSZ) return;
    int m = i >> 16;
    int e = i & (WSZ - 1);
    const float* src = (m == 0) ? w0 : (m == 1) ? w1 : (m == 2) ? w2 : w3;
    float v = src[e];
    __nv_bfloat16 h = __float2bfloat16(v);
    float lv = v - __bfloat162float(h);
    g_wh[m][e] = h;
    g_wl[m][e] = __float2bfloat16(lv);
}

__global__ void __launch_bounds__(256) k_scan1() {
    __shared__ int sh[256];
    int i = blockIdx.x * 256 + threadIdx.x;
    sh[threadIdx.x] = (i < NN) ? g_deg[i] : 0;
    __syncthreads();
    for (int d = 128; d > 0; d >>= 1) {
        if (threadIdx.x < d) sh[threadIdx.x] += sh[threadIdx.x + d];
        __syncthreads();
    }
    if (threadIdx.x == 0) g_part[blockIdx.x] = sh[0];
}

__global__ void __launch_bounds__(512) k_scan2b() {
    __shared__ int sh[512];
    int tid = threadIdx.x;
    int own = (tid < SCB) ? g_part[tid] : 0;
    sh[tid] = own;
    __syncthreads();
    for (int d = 1; d < 512; d <<= 1) {
        int v = (tid >= d) ? sh[tid - d] : 0;
        __syncthreads();
        sh[tid] += v;
        __syncthreads();
    }
    if (tid < SCB) g_part[tid] = sh[tid] - own;
}

__global__ void __launch_bounds__(256) k_scan3() {
    __shared__ int sh[256];
    int i = blockIdx.x * 256 + threadIdx.x;
    int own = (i < NN) ? g_deg[i] : 0;
    sh[threadIdx.x] = own;
    __syncthreads();
    for (int d = 1; d < 256; d <<= 1) {
        int v = (threadIdx.x >= d) ? sh[threadIdx.x - d] : 0;
        __syncthreads();
        sh[threadIdx.x] += v;
        __syncthreads();
    }
    if (i < NN) g_off[i] = g_part[blockIdx.x] + sh[threadIdx.x] - own;
    if (i == NN - 1) g_off[NN] = EE;
}

__global__ void k_scatter(const int* __restrict__ ei) {
    int e = blockIdx.x * blockDim.x + threadIdx.x;
    if (e < EE) {
        int t = ei[EE + e];
        int s = ei[e];
        if (t >= 0 && t < NN && s >= 0 && s < NN) {
            int p = atomicAdd(&g_cur[t], 1);
            g_srcs[g_off[t] + p] = s;
        }
    }
}

// ---------------- mean aggregation: fp16 gather, fp32 accum/out, 8-edge unroll ----------------
__global__ void __launch_bounds__(256) k_agg16(const uint2* __restrict__ x16,
                                               float4* __restrict__ out4) {
    int node = blockIdx.x * 4 + (threadIdx.x >> 6);
    int t = threadIdx.x & 63;
    if (node >= NN) return;
    int beg = g_off[node];
    int end = g_off[node + 1];

    float4 a = make_float4(0.f, 0.f, 0.f, 0.f);
    float4 b = make_float4(0.f, 0.f, 0.f, 0.f);
    int i = beg;
    for (; i + 8 <= end; i += 8) {
        uint2 v0 = x16[(size_t)g_srcs[i]     * D4 + t];
        uint2 v1 = x16[(size_t)g_srcs[i + 1] * D4 + t];
        uint2 v2 = x16[(size_t)g_srcs[i + 2] * D4 + t];
        uint2 v3 = x16[(size_t)g_srcs[i + 3] * D4 + t];
        uint2 v4 = x16[(size_t)g_srcs[i + 4] * D4 + t];
        uint2 v5 = x16[(size_t)g_srcs[i + 5] * D4 + t];
        uint2 v6 = x16[(size_t)g_srcs[i + 6] * D4 + t];
        uint2 v7 = x16[(size_t)g_srcs[i + 7] * D4 + t];
        float2 f;
        f = __half22float2(*(__half2*)&v0.x); a.x += f.x; a.y += f.y;
        f = __half22float2(*(__half2*)&v0.y); a.z += f.x; a.w += f.y;
        f = __half22float2(*(__half2*)&v1.x); b.x += f.x; b.y += f.y;
        f = __half22float2(*(__half2*)&v1.y); b.z += f.x; b.w += f.y;
        f = __half22float2(*(__half2*)&v2.x); a.x += f.x; a.y += f.y;
        f = __half22float2(*(__half2*)&v2.y); a.z += f.x; a.w += f.y;
        f = __half22float2(*(__half2*)&v3.x); b.x += f.x; b.y += f.y;
        f = __half22float2(*(__half2*)&v3.y); b.z += f.x; b.w += f.y;
        f = __half22float2(*(__half2*)&v4.x); a.x += f.x; a.y += f.y;
        f = __half22float2(*(__half2*)&v4.y); a.z += f.x; a.w += f.y;
        f = __half22float2(*(__half2*)&v5.x); b.x += f.x; b.y += f.y;
        f = __half22float2(*(__half2*)&v5.y); b.z += f.x; b.w += f.y;
        f = __half22float2(*(__half2*)&v6.x); a.x += f.x; a.y += f.y;
        f = __half22float2(*(__half2*)&v6.y); a.z += f.x; a.w += f.y;
        f = __half22float2(*(__half2*)&v7.x); b.x += f.x; b.y += f.y;
        f = __half22float2(*(__half2*)&v7.y); b.z += f.x; b.w += f.y;
    }
    for (; i < end; i++) {
        uint2 v = x16[(size_t)g_srcs[i] * D4 + t];
        float2 f;
        f = __half22float2(*(__half2*)&v.x); a.x += f.x; a.y += f.y;
        f = __half22float2(*(__half2*)&v.y); a.z += f.x; a.w += f.y;
    }
    float inv = 1.0f / fmaxf((float)(end - beg), 1.0f);
    float4 r;
    r.x = (a.x + b.x) * inv;
    r.y = (a.y + b.y) * inv;
    r.z = (a.z + b.z) * inv;
    r.w = (a.w + b.w) * inv;
    out4[(size_t)node * D4 + t] = r;
}

// ---------------- tensor-core fused dual GEMM: DOUBLE-BUFFERED, 1 sync/tile ----------------
#define BM 128
#define BN 128
#define BK 32
#define APAD 40
#define BPAD 136
#define A_ST (BM * APAD)            // 5120 bf16 per A buffer
#define B_ST (BK * BPAD)            // 4352 bf16 per B buffer
#define SMEM_ELEMS (4 * A_ST + 4 * B_ST)   // 37888 bf16 = 75776 B

__device__ __forceinline__ unsigned sptr(const void* p) {
    return (unsigned)__cvta_generic_to_shared(p);
}

__device__ __forceinline__ void ldm_x4(unsigned* r, unsigned addr) {
    asm volatile("ldmatrix.sync.aligned.m8n8.x4.shared.b16 {%0,%1,%2,%3}, [%4];"
                 : "=r"(r[0]), "=r"(r[1]), "=r"(r[2]), "=r"(r[3])
                 : "r"(addr));
}

__device__ __forceinline__ void ldm_x4t(unsigned* r, unsigned addr) {
    asm volatile("ldmatrix.sync.aligned.m8n8.x4.trans.shared.b16 {%0,%1,%2,%3}, [%4];"
                 : "=r"(r[0]), "=r"(r[1]), "=r"(r[2]), "=r"(r[3])
                 : "r"(addr));
}

__device__ __forceinline__ void mma_bf16(float* d, const unsigned* a, const unsigned* b) {
    asm volatile("mma.sync.aligned.m16n8k16.row.col.f32.bf16.bf16.f32 "
                 "{%0,%1,%2,%3}, {%4,%5,%6,%7}, {%8,%9}, {%0,%1,%2,%3};"
                 : "+f"(d[0]), "+f"(d[1]), "+f"(d[2]), "+f"(d[3])
                 : "r"(a[0]), "r"(a[1]), "r"(a[2]), "r"(a[3]),
                   "r"(b[0]), "r"(b[1]));
}

__device__ __forceinline__ void split2(float x, float y, unsigned* hi, unsigned* lo) {
    __nv_bfloat16 hx = __float2bfloat16(x);
    __nv_bfloat16 hy = __float2bfloat16(y);
    float lx = x - __bfloat162float(hx);
    float ly = y - __bfloat162float(hy);
    __nv_bfloat162 h2 = __halves2bfloat162(hx, hy);
    __nv_bfloat162 l2 = __halves2bfloat162(__float2bfloat16(lx), __float2bfloat16(ly));
    *hi = *(unsigned*)&h2;
    *lo = *(unsigned*)&l2;
}

__global__ void __launch_bounds__(256) k_gemm_tc(const float* __restrict__ A,
                                                 const float* __restrict__ X,
                                                 const __nv_bfloat16* __restrict__ W1h,
                                                 const __nv_bfloat16* __restrict__ W1l,
                                                 const __nv_bfloat16* __restrict__ W2h,
                                                 const __nv_bfloat16* __restrict__ W2l,
                                                 const float* __restrict__ bias,
                                                 float* __restrict__ O,
                                                 __half* __restrict__ O16,
                                                 int do_relu) {
    extern __shared__ __nv_bfloat16 sm[];
    int tid = threadIdx.x;
    int wid = tid >> 5;
    int lane = tid & 31;
    int warp_m = wid >> 1;
    int warp_n = wid & 1;
    int row0 = blockIdx.y * BM;
    int col0 = blockIdx.x * BN;

    float acc[2][8][4];
    for (int i = 0; i < 2; i++) {
        for (int j = 0; j < 8; j++) {
            for (int q = 0; q < 4; q++) {
                acc[i][j][q] = 0.f;
            }
        }
    }

    int ar = tid >> 1;
    int ac = (tid & 1) * 16;
    int br = tid >> 3;
    int bc = (tid & 7) * 16;
    int gr = row0 + ar;

    // tile loader: ti in [0,16); phase = ti>>3; kt = (ti&7)*BK; stage s
    auto load_tile = [&](int ti, int s) {
        const float* Ain = (ti < 8) ? A : X;
        const __nv_bfloat16* Winh = (ti < 8) ? W1h : W2h;
        const __nv_bfloat16* Winl = (ti < 8) ? W1l : W2l;
        int kt = (ti & 7) * BK;
        __nv_bfloat16* AhS = sm + s * 2 * A_ST;
        __nv_bfloat16* AlS = AhS + A_ST;
        __nv_bfloat16* BhS = sm + 4 * A_ST + s * 2 * B_ST;
        __nv_bfloat16* BlS = BhS + B_ST;

        const float* asrc = Ain + (size_t)gr * DD + kt + ac;
        for (int q = 0; q < 4; q++) {
            float4 v = make_float4(0.f, 0.f, 0.f, 0.f);
            if (gr < NN) v = *(const float4*)(asrc + q * 4);
            unsigned h01, l01, h23, l23;
            split2(v.x, v.y, &h01, &l01);
            split2(v.z, v.w, &h23, &l23);
            int c = ar * APAD + ac + q * 4;
            *(unsigned*)&AhS[c]     = h01;
            *(unsigned*)&AhS[c + 2] = h23;
            *(unsigned*)&AlS[c]     = l01;
            *(unsigned*)&AlS[c + 2] = l23;
        }
        size_t off = (size_t)(kt + br) * DD + col0 + bc;
        const __nv_bfloat16* hsrc = Winh + off;
        const __nv_bfloat16* lsrc = Winl + off;
        for (int q = 0; q < 4; q++) {
            uint2 hv = *(const uint2*)(hsrc + q * 4);
            uint2 lv = *(const uint2*)(lsrc + q * 4);
            int c = br * BPAD + bc + q * 4;
            *(uint2*)&BhS[c] = hv;
            *(uint2*)&BlS[c] = lv;
        }
    };

    load_tile(0, 0);
    __syncthreads();

    for (int ti = 0; ti < 16; ti++) {
        int s = ti & 1;
        if (ti < 15) load_tile(ti + 1, s ^ 1);

        __nv_bfloat16* AhS = sm + s * 2 * A_ST;
        __nv_bfloat16* AlS = AhS + A_ST;
        __nv_bfloat16* BhS = sm + 4 * A_ST + s * 2 * B_ST;
        __nv_bfloat16* BlS = BhS + B_ST;

        for (int ks = 0; ks < BK; ks += 16) {
            unsigned ah[2][4];
            unsigned al[2][4];
            for (int i = 0; i < 2; i++) {
                int r = warp_m * 32 + i * 16 + (lane & 15);
                int c = r * APAD + ks + ((lane >> 4) << 3);
                ldm_x4(ah[i], sptr(&AhS[c]));
                ldm_x4(al[i], sptr(&AlS[c]));
            }
            unsigned bh[8][2];
            unsigned bl[8][2];
            for (int j2 = 0; j2 < 4; j2++) {
                int r = ks + (lane & 15);
                int c = r * BPAD + warp_n * 64 + j2 * 16 + ((lane >> 4) << 3);
                unsigned t4[4];
                ldm_x4t(t4, sptr(&BhS[c]));
                bh[j2 * 2][0]     = t4[0];
                bh[j2 * 2][1]     = t4[1];
                bh[j2 * 2 + 1][0] = t4[2];
                bh[j2 * 2 + 1][1] = t4[3];
                ldm_x4t(t4, sptr(&BlS[c]));
                bl[j2 * 2][0]     = t4[0];
                bl[j2 * 2][1]     = t4[1];
                bl[j2 * 2 + 1][0] = t4[2];
                bl[j2 * 2 + 1][1] = t4[3];
            }
            for (int i = 0; i < 2; i++) {
                for (int j = 0; j < 8; j++) {
                    mma_bf16(acc[i][j], ah[i], bh[j]);
                    mma_bf16(acc[i][j], ah[i], bl[j]);
                    mma_bf16(acc[i][j], al[i], bh[j]);
                }
            }
        }
        __syncthreads();
    }

    for (int j = 0; j < 8; j++) {
        int c = col0 + warp_n * 64 + j * 8 + (lane & 3) * 2;
        float2 bb = *(const float2*)(bias + c);
        for (int i = 0; i < 2; i++) {
            int r = row0 + warp_m * 32 + i * 16 + (lane >> 2);
            float v0 = acc[i][j][0] + bb.x;
            float v1 = acc[i][j][1] + bb.y;
            float v2 = acc[i][j][2] + bb.x;
            float v3 = acc[i][j][3] + bb.y;
            if (do_relu) {
                v0 = fmaxf(v0, 0.f);
                v1 = fmaxf(v1, 0.f);
                v2 = fmaxf(v2, 0.f);
                v3 = fmaxf(v3, 0.f);
            }
            if (r < NN) {
                *(float2*)(O + (size_t)r * DD + c) = make_float2(v0, v1);
                if (O16) {
                    __half2 hh = __floats2half2_rn(v0, v1);
                    *(__half2*)(O16 + (size_t)r * DD + c) = hh;
                }
            }
            if (r + 8 < NN) {
                *(float2*)(O + (size_t)(r + 8) * DD + c) = make_float2(v2, v3);
                if (O16) {
                    __half2 hh = __floats2half2_rn(v2, v3);
                    *(__half2*)(O16 + (size_t)(r + 8) * DD + c) = hh;
                }
            }
        }
    }
}

extern "C" void kernel_launch(void* const* d_in, const int* in_sizes, int n_in,
                              void* d_out, int out_size) {
    const float* x   = (const float*)d_in[0];
    const int*   ei  = (const int*)d_in[1];
    const float* Wl1 = (const float*)d_in[2];
    const float* b1  = (const float*)d_in[3];
    const float* Wr1 = (const float*)d_in[4];
    const float* Wl2 = (const float*)d_in[5];
    const float* b2  = (const float*)d_in[6];
    const float* Wr2 = (const float*)d_in[7];
    float*       out = (float*)d_out;

    void* agg_p = 0;
    void* h_p = 0;
    void* x16_p = 0;
    void* h16_p = 0;
    void* wh_p = 0;
    void* wl_p = 0;
    cudaGetSymbolAddress(&agg_p, g_agg4);
    cudaGetSymbolAddress(&h_p, g_h4);
    cudaGetSymbolAddress(&x16_p, g_x16);
    cudaGetSymbolAddress(&h16_p, g_h16);
    cudaGetSymbolAddress(&wh_p, g_wh);
    cudaGetSymbolAddress(&wl_p, g_wl);
    float4* agg4 = (float4*)agg_p;
    float4* h4   = (float4*)h_p;
    uint2*  x16  = (uint2*)x16_p;
    uint2*  h16  = (uint2*)h16_p;
    __nv_bfloat16* wh = (__nv_bfloat16*)wh_p;
    __nv_bfloat16* wl = (__nv_bfloat16*)wl_p;

    static int smem_set = 0;
    if (!smem_set) {
        cudaFuncSetAttribute(k_gemm_tc, cudaFuncAttributeMaxDynamicSharedMemorySize,
                             SMEM_ELEMS * 2);
        smem_set = 1;
    }

    k_zero<<<(NN + 255) / 256, 256>>>();
    k_deg_cvt<<<(NN * D4 + 255) / 256, 256>>>(ei, (const float4*)x, x16);
    k_wsplit<<<(4 * WSZ + 255) / 256, 256>>>(Wl1, Wr1, Wl2, Wr2);
    k_scan1<<<SCB, 256>>>();
    k_scan2b<<<1, 512>>>();
    k_scan3<<<SCB, 256>>>();
    k_scatter<<<(EE + 255) / 256, 256>>>(ei);

    dim3 ggrid(DD / BN, (NN + BM - 1) / BM);   // (2, 782)
    int smem_bytes = SMEM_ELEMS * 2;           // 75776 B

    // layer 1: agg(x16) -> agg4; gemm(A=agg4 w/ Wl1, X=x w/ Wr1) -> h4 + h16 (+relu)
    k_agg16<<<(NN + 3) / 4, 256>>>(x16, agg4);
    k_gemm_tc<<<ggrid, 256, smem_bytes>>>((const float*)agg4, x,
                                          wh + 0 * WSZ, wl + 0 * WSZ,
                                          wh + 1 * WSZ, wl + 1 * WSZ,
                                          b1, (float*)h4, (__half*)h16, 1);

    // layer 2: agg(h16) -> agg4; gemm(A=agg4 w/ Wl2, X=h4 w/ Wr2) -> out
    k_agg16<<<(NN + 3) / 4, 256>>>(h16, agg4);
    k_gemm_tc<<<ggrid, 256, smem_bytes>>>((const float*)agg4, (const float*)h4,
                                          wh + 2 * WSZ, wl + 2 * WSZ,
                                          wh + 3 * WSZ, wl + 3 * WSZ,
                                          b2, out, (__half*)0, 0);
}